// round 1
// baseline (speedup 1.0000x reference)
#include <cuda_runtime.h>
#include <cstdint>
#include <cstddef>

// Problem shape (fixed by the dataset)
#define S 8192
#define M 2048
#define E 64

#define KSPLIT 4
#define KSLICE (M / KSPLIT)      // 512
#define KC 32
#define TOKB 256                 // tokens per compute block
#define NCOMPUTE ((S / TOKB) * KSPLIT)   // 32 * 4 = 128
#define NZERO 128

typedef unsigned long long u64;

// Scratch (device globals — no allocations allowed)
__device__ float g_logits[(size_t)S * E];   // 2 MB, split-K accumulator
__device__ float g_colsum[E];
__device__ int   g_expert[S];
__device__ float g_gate[S];

__device__ __forceinline__ u64 pack2(float x) {
    u64 r;
    asm("mov.b64 %0, {%1, %1};" : "=l"(r) : "f"(x));
    return r;
}
__device__ __forceinline__ void ffma2(u64 &d, u64 a, u64 b) {
    asm("fma.rn.f32x2 %0, %1, %2, %0;" : "+l"(d) : "l"(a), "l"(b));
}

// ---------------------------------------------------------------------------
// init: zero split-K logits accumulator + column sums (graph replays need
// re-zeroing every call)
// ---------------------------------------------------------------------------
__global__ void init_kernel() {
    int i = blockIdx.x * blockDim.x + threadIdx.x;
    float4 z = make_float4(0.f, 0.f, 0.f, 0.f);
    float4* p = (float4*)g_logits;
    const int n4 = (S * E) / 4;   // 131072
    for (int j = i; j < n4; j += gridDim.x * blockDim.x) p[j] = z;
    if (i < E) g_colsum[i] = 0.f;
}

// ---------------------------------------------------------------------------
// Fused kernel: blocks [0, NCOMPUTE) compute logits (split-K GEMM),
// blocks [NCOMPUTE, NCOMPUTE+NZERO) zero the entire output buffer.
// Role split by bid range so CLC's contiguous map pairs one compute + one
// zero block per SM (b and b+148 land on the same SM; 148 > 128 so every
// compute block gets its own SM).
// ---------------------------------------------------------------------------
__global__ void fused_gemm_zero(const float* __restrict__ in,
                                const float* __restrict__ wgt,
                                float* __restrict__ out,
                                size_t out_elems) {
    const int bid = blockIdx.x;
    const int tid = threadIdx.x;

    if (bid >= NCOMPUTE) {
        // ---- zero role: stream float4 zeros over the whole output ----
        const int zid = bid - NCOMPUTE;
        const size_t total4 = out_elems >> 2;
        float4 z = make_float4(0.f, 0.f, 0.f, 0.f);
        float4* o4 = (float4*)out;
        for (size_t i = (size_t)zid * 256 + tid; i < total4;
             i += (size_t)NZERO * 256)
            o4[i] = z;
        if (zid == 0 && tid == 0) {
            for (size_t r = total4 * 4; r < out_elems; ++r) out[r] = 0.f;
        }
        return;
    }

    // ---- compute role ----
    const int cid = bid;
    const int tb  = cid & (S / TOKB - 1);   // token block 0..31
    const int ks  = cid / (S / TOKB);       // k-split 0..3
    const int s0  = tb * TOKB;
    const int k0  = ks * KSLICE;

    __shared__ float As[KC][TOKB + 1];   // [32][257], +1 pad for STS banks
    __shared__ float Bs[KC][E];          // [32][64], read warp-uniform

    const int warp = tid >> 5;
    const int myTok = s0 + warp * 32 + (tid & 31);

    u64 acc[E / 2];
#pragma unroll
    for (int j = 0; j < E / 2; ++j) acc[j] = 0ull;

    const int a_tok = tid >> 3;   // 0..31 within a pass
    const int a_kq  = tid & 7;    // which float4 of the 32-k row

    for (int c = 0; c < KSLICE / KC; ++c) {
        const int kc = k0 + c * KC;
        // Load A chunk (256 tokens x 32 k), coalesced: 8 lanes per token row
#pragma unroll
        for (int p = 0; p < 8; ++p) {
            int t = p * 32 + a_tok;
            float4 v = *(const float4*)(in + (size_t)(s0 + t) * M + kc + a_kq * 4);
            As[a_kq * 4 + 0][t] = v.x;
            As[a_kq * 4 + 1][t] = v.y;
            As[a_kq * 4 + 2][t] = v.z;
            As[a_kq * 4 + 3][t] = v.w;
        }
        // Load B chunk (64 experts x 32 k)
#pragma unroll
        for (int r = 0; r < 2; ++r) {
            int q = tid * 2 + r;
            int e = q >> 3, kq = q & 7;
            float4 v = *(const float4*)(wgt + (size_t)e * M + kc + kq * 4);
            Bs[kq * 4 + 0][e] = v.x;
            Bs[kq * 4 + 1][e] = v.y;
            Bs[kq * 4 + 2][e] = v.z;
            Bs[kq * 4 + 3][e] = v.w;
        }
        __syncthreads();
#pragma unroll
        for (int kk = 0; kk < KC; ++kk) {
            float a = As[kk][tid & 255];        // = As[kk][warp*32+lane]
            u64 aa = pack2(a);
            const u64* brow = (const u64*)(&Bs[kk][0]);
#pragma unroll
            for (int j = 0; j < E / 2; ++j) ffma2(acc[j], aa, brow[j]);
        }
        __syncthreads();
    }

    // Accumulate partial logits (split-K) — RED.F32, no return needed
    float* lrow = g_logits + (size_t)myTok * E;
#pragma unroll
    for (int j = 0; j < E / 2; ++j) {
        float2 v = *(float2*)&acc[j];
        atomicAdd(lrow + 2 * j + 0, v.x);
        atomicAdd(lrow + 2 * j + 1, v.y);
    }
}

// ---------------------------------------------------------------------------
// Softmax + argmax (first-max tie-break, matching jnp.argmax) + column sums
// ---------------------------------------------------------------------------
__global__ void softmax_kernel() {
    const int tid = threadIdx.x;
    const int s   = blockIdx.x * 256 + tid;

    __shared__ float smax[256];
    __shared__ float sinv[256];

    float x[E];
    const float4* row = (const float4*)(g_logits + (size_t)s * E);
#pragma unroll
    for (int j = 0; j < E / 4; ++j) {
        float4 v = row[j];
        x[4 * j + 0] = v.x; x[4 * j + 1] = v.y;
        x[4 * j + 2] = v.z; x[4 * j + 3] = v.w;
    }
    float mx = x[0];
    int am = 0;
#pragma unroll
    for (int j = 1; j < E; ++j) {
        if (x[j] > mx) { mx = x[j]; am = j; }   // strict > keeps first max
    }
    float sum = 0.f;
#pragma unroll
    for (int j = 0; j < E; ++j) sum += __expf(x[j] - mx);
    float inv = 1.f / sum;

    g_expert[s] = am;
    g_gate[s]   = inv;          // gate at argmax = exp(0)/sum
    smax[tid]   = mx;
    sinv[tid]   = inv;
    __syncthreads();

    // column sums of full softmax gates (for l_aux): expert-major pass
    const int e   = tid & 63;
    const int grp = tid >> 6;               // 0..3, 64 tokens each
    const int base = blockIdx.x * 256 + grp * 64;
    float part = 0.f;
#pragma unroll 4
    for (int i = 0; i < 64; ++i) {
        float lg = g_logits[(size_t)(base + i) * E + e];
        part += __expf(lg - smax[grp * 64 + i]) * sinv[grp * 64 + i];
    }
    atomicAdd(&g_colsum[e], part);
}

// ---------------------------------------------------------------------------
// Per-expert ordered scan (== cumsum capacity filter), scatter nonzeros,
// exp_counts, and l_aux.
// One warp per expert; ballot prefix preserves token order exactly.
// ---------------------------------------------------------------------------
__global__ void scan_kernel(float* __restrict__ out, size_t SEC, int CAPV) {
    const int e    = blockIdx.x;
    const int lane = threadIdx.x;
    int cnt = 0;
    for (int base = 0; base < S; base += 32) {
        int idx = g_expert[base + lane];
        bool m = (idx == e);
        unsigned b = __ballot_sync(0xffffffffu, m);
        if (m) {
            int pos = cnt + __popc(b & ((1u << lane) - 1u));
            if (pos < CAPV) {
                size_t o = 1 + ((size_t)(base + lane) * E + e) * (size_t)CAPV + pos;
                out[o]       = g_gate[base + lane];   // combine_weights
                out[o + SEC] = 1.0f;                  // dispatch_mask
            }
        }
        cnt += __popc(b);
    }
    if (lane == 0) {
        out[1 + 2 * SEC + e] = (float)cnt;            // exp_counts (pre-filter)
        // l_aux = E * sum_e (colsum_e/S) * (cnt_e/S)
        float term = g_colsum[e] * (float)cnt *
                     ((float)E / ((float)S * (float)S));
        atomicAdd(out, term);
    }
}

// ---------------------------------------------------------------------------
extern "C" void kernel_launch(void* const* d_in, const int* in_sizes, int n_in,
                              void* d_out, int out_size) {
    const float* in  = (const float*)d_in[0];
    const float* wgt = (const float*)d_in[1];
    float* out = (float*)d_out;

    // Derive capacity from out_size; fall back to the analytic value (128).
    long long c = ((long long)out_size - 1 - E) / (2LL * S * E);
    int CAPV = 128;
    if (c > 0 && (1 + 2LL * S * E * c + E) == (long long)out_size)
        CAPV = (int)c;
    size_t SEC = (size_t)S * E * (size_t)CAPV;

    init_kernel<<<128, 256>>>();
    fused_gemm_zero<<<NCOMPUTE + NZERO, 256>>>(in, wgt, out, (size_t)out_size);
    softmax_kernel<<<S / 256, 256>>>();
    scan_kernel<<<E, 32>>>(out, SEC, CAPV);
}

// round 2
// speedup vs baseline: 1.4721x; 1.4721x over previous
#include <cuda_runtime.h>
#include <cstdint>
#include <cstddef>

// Problem shape (fixed by the dataset)
#define S 8192
#define M 2048
#define E 64

#define KSPLIT 4
#define KSLICE (M / KSPLIT)      // 512
#define KC 32
#define TOKB 256                 // tokens per compute block
#define NCOMPUTE ((S / TOKB) * KSPLIT)   // 32 * 4 = 128
#define NZERO 128
#define NCHUNK (S / 32)          // 256 warp-sized token chunks

typedef unsigned long long u64;

// Scratch (device globals — no allocations allowed)
__device__ float g_logits[(size_t)S * E];   // 2 MB: logits, then overwritten with gates
__device__ float g_colsum[E];
__device__ int   g_expert[S];
__device__ float g_gate[S];
__device__ int   g_rank[S];                  // rank within 32-token chunk, same expert
__device__ int   g_wcount[NCHUNK * E];       // per-chunk per-expert counts
__device__ int   g_base[NCHUNK * E];         // exclusive prefix of g_wcount over chunks

__device__ __forceinline__ u64 pack2(float x) {
    u64 r;
    asm("mov.b64 %0, {%1, %1};" : "=l"(r) : "f"(x));
    return r;
}
__device__ __forceinline__ void ffma2(u64 &d, u64 a, u64 b) {
    asm("fma.rn.f32x2 %0, %1, %2, %0;" : "+l"(d) : "l"(a), "l"(b));
}

// ---------------------------------------------------------------------------
// init: zero split-K logits accumulator, colsum, chunk histograms
// ---------------------------------------------------------------------------
__global__ void init_kernel() {
    int i = blockIdx.x * blockDim.x + threadIdx.x;
    float4 z = make_float4(0.f, 0.f, 0.f, 0.f);
    float4* p = (float4*)g_logits;
    const int n4 = (S * E) / 4;   // 131072
    for (int j = i; j < n4; j += gridDim.x * blockDim.x) p[j] = z;
    int4* w4 = (int4*)g_wcount;
    const int nw4 = (NCHUNK * E) / 4;  // 4096
    for (int j = i; j < nw4; j += gridDim.x * blockDim.x)
        w4[j] = make_int4(0, 0, 0, 0);
    if (i < E) g_colsum[i] = 0.f;
}

// ---------------------------------------------------------------------------
// Fused kernel: blocks [0, NCOMPUTE) compute logits (split-K GEMM),
// blocks [NCOMPUTE, NCOMPUTE+NZERO) zero the entire output buffer.
// __launch_bounds__(256, 2) keeps regs <= 128 so ALL 256 blocks are
// co-resident in wave 1 (2 blocks/SM) -> zeroing overlaps the GEMM.
// ---------------------------------------------------------------------------
__global__ void __launch_bounds__(256, 2)
fused_gemm_zero(const float* __restrict__ in,
                const float* __restrict__ wgt,
                float* __restrict__ out,
                size_t out_elems) {
    const int bid = blockIdx.x;
    const int tid = threadIdx.x;

    if (bid >= NCOMPUTE) {
        // ---- zero role: stream float4 zeros over the whole output ----
        const int zid = bid - NCOMPUTE;
        const size_t total4 = out_elems >> 2;
        float4 z = make_float4(0.f, 0.f, 0.f, 0.f);
        float4* o4 = (float4*)out;
        for (size_t i = (size_t)zid * 256 + tid; i < total4;
             i += (size_t)NZERO * 256)
            __stcs(o4 + i, z);
        if (zid == 0 && tid == 0) {
            for (size_t r = total4 * 4; r < out_elems; ++r)
                __stcs(out + r, 0.f);
        }
        return;
    }

    // ---- compute role ----
    const int cid = bid;
    const int tb  = cid & (S / TOKB - 1);   // token block 0..31
    const int ks  = cid / (S / TOKB);       // k-split 0..3
    const int s0  = tb * TOKB;
    const int k0  = ks * KSLICE;

    __shared__ float As[KC][TOKB + 1];   // [32][257], +1 pad for STS banks
    __shared__ float Bs[KC][E];          // [32][64], read warp-uniform

    const int warp = tid >> 5;
    const int myTok = s0 + warp * 32 + (tid & 31);

    u64 acc[E / 2];
#pragma unroll
    for (int j = 0; j < E / 2; ++j) acc[j] = 0ull;

    const int a_tok = tid >> 3;   // 0..31 within a pass
    const int a_kq  = tid & 7;    // which float4 of the 32-k row

    for (int c = 0; c < KSLICE / KC; ++c) {
        const int kc = k0 + c * KC;
        // Load A chunk (256 tokens x 32 k), coalesced: 8 lanes per token row
#pragma unroll
        for (int p = 0; p < 8; ++p) {
            int t = p * 32 + a_tok;
            float4 v = *(const float4*)(in + (size_t)(s0 + t) * M + kc + a_kq * 4);
            As[a_kq * 4 + 0][t] = v.x;
            As[a_kq * 4 + 1][t] = v.y;
            As[a_kq * 4 + 2][t] = v.z;
            As[a_kq * 4 + 3][t] = v.w;
        }
        // Load B chunk (64 experts x 32 k)
#pragma unroll
        for (int r = 0; r < 2; ++r) {
            int q = tid * 2 + r;
            int e = q >> 3, kq = q & 7;
            float4 v = *(const float4*)(wgt + (size_t)e * M + kc + kq * 4);
            Bs[kq * 4 + 0][e] = v.x;
            Bs[kq * 4 + 1][e] = v.y;
            Bs[kq * 4 + 2][e] = v.z;
            Bs[kq * 4 + 3][e] = v.w;
        }
        __syncthreads();
#pragma unroll
        for (int kk = 0; kk < KC; ++kk) {
            float a = As[kk][tid & 255];
            u64 aa = pack2(a);
            const u64* brow = (const u64*)(&Bs[kk][0]);
#pragma unroll
            for (int j = 0; j < E / 2; ++j) ffma2(acc[j], aa, brow[j]);
        }
        __syncthreads();
    }

    // Accumulate partial logits (split-K) — RED.F32, spread addresses
    float* lrow = g_logits + (size_t)myTok * E;
#pragma unroll
    for (int j = 0; j < E / 2; ++j) {
        float2 v = *(float2*)&acc[j];
        atomicAdd(lrow + 2 * j + 0, v.x);
        atomicAdd(lrow + 2 * j + 1, v.y);
    }
}

// ---------------------------------------------------------------------------
// Softmax + argmax (first-max tie-break) + per-chunk ranks/histograms.
// Writes normalized gates back over g_logits, then column-sums them for
// l_aux (no second expf pass).
// ---------------------------------------------------------------------------
__global__ void softmax_kernel() {
    const int tid = threadIdx.x;
    const int s   = blockIdx.x * 256 + tid;
    const int lane = tid & 31;

    float x[E];
    float4* row = (float4*)(g_logits + (size_t)s * E);
#pragma unroll
    for (int j = 0; j < E / 4; ++j) {
        float4 v = row[j];
        x[4 * j + 0] = v.x; x[4 * j + 1] = v.y;
        x[4 * j + 2] = v.z; x[4 * j + 3] = v.w;
    }
    float mx = x[0];
    int am = 0;
#pragma unroll
    for (int j = 1; j < E; ++j) {
        if (x[j] > mx) { mx = x[j]; am = j; }   // strict > keeps first max
    }
    float sum = 0.f;
#pragma unroll
    for (int j = 0; j < E; ++j) sum += __expf(x[j] - mx);
    float inv = 1.f / sum;

    g_expert[s] = am;
    g_gate[s]   = inv;          // gate at argmax = exp(0)/sum

    // Intra-warp (32-token-chunk) rank among same-expert tokens; token order
    // == lane order, so popc over lower lanes == cumsum semantics.
    unsigned grp = __match_any_sync(0xffffffffu, am);
    int rank = __popc(grp & ((1u << lane) - 1u));
    g_rank[s] = rank;
    if (rank == 0) g_wcount[(s >> 5) * E + am] = __popc(grp);

    // Overwrite logits row with normalized gates
#pragma unroll
    for (int j = 0; j < E / 4; ++j) {
        float4 v;
        v.x = __expf(x[4 * j + 0] - mx) * inv;
        v.y = __expf(x[4 * j + 1] - mx) * inv;
        v.z = __expf(x[4 * j + 2] - mx) * inv;
        v.w = __expf(x[4 * j + 3] - mx) * inv;
        row[j] = v;
    }
    __syncthreads();   // orders this block's global gate writes for pass 2

    // Column sums of gates (for l_aux), tokens of THIS block only
    const int e   = tid & 63;
    const int grp2 = tid >> 6;               // 0..3, 64 tokens each
    const int base = blockIdx.x * 256 + grp2 * 64;
    float part = 0.f;
#pragma unroll 4
    for (int i = 0; i < 64; ++i)
        part += g_logits[(size_t)(base + i) * E + e];
    atomicAdd(&g_colsum[e], part);
}

// ---------------------------------------------------------------------------
// Per-expert exclusive prefix over the 256 chunk counts (one block/expert),
// plus exp_counts and l_aux (counts are pre-capacity, matching reference).
// ---------------------------------------------------------------------------
__global__ void base_kernel(float* __restrict__ out, size_t SEC) {
    const int e = blockIdx.x;
    const int c = threadIdx.x;          // chunk 0..255
    const int lane = c & 31, w = c >> 5;

    int v = g_wcount[c * E + e];
    int x = v;
#pragma unroll
    for (int d = 1; d < 32; d <<= 1) {
        int t = __shfl_up_sync(0xffffffffu, x, d);
        if (lane >= d) x += t;
    }
    __shared__ int wsum[8];
    if (lane == 31) wsum[w] = x;
    __syncthreads();
    if (c == 0) {
        int a = 0;
#pragma unroll
        for (int i = 0; i < 8; ++i) { int t = wsum[i]; wsum[i] = a; a += t; }
    }
    __syncthreads();
    int excl = x - v + wsum[w];
    g_base[c * E + e] = excl;

    if (c == 255) {
        int tot = excl + v;
        out[1 + 2 * SEC + e] = (float)tot;        // exp_counts
        float term = g_colsum[e] * (float)tot *
                     ((float)E / ((float)S * (float)S));
        atomicAdd(out, term);                     // l_aux
    }
}

// ---------------------------------------------------------------------------
// Scatter the <= S nonzeros into the (already-zeroed) output.
// ---------------------------------------------------------------------------
__global__ void scatter_kernel(float* __restrict__ out, size_t SEC, int CAPV) {
    const int s = blockIdx.x * 256 + threadIdx.x;
    const int e = g_expert[s];
    const int pos = g_base[(s >> 5) * E + e] + g_rank[s];
    if (pos < CAPV) {
        size_t o = 1 + ((size_t)s * E + e) * (size_t)CAPV + pos;
        out[o]       = g_gate[s];   // combine_weights
        out[o + SEC] = 1.0f;        // dispatch_mask
    }
}

// ---------------------------------------------------------------------------
extern "C" void kernel_launch(void* const* d_in, const int* in_sizes, int n_in,
                              void* d_out, int out_size) {
    const float* in  = (const float*)d_in[0];
    const float* wgt = (const float*)d_in[1];
    float* out = (float*)d_out;

    // Derive capacity from out_size; fall back to the analytic value (128).
    long long c = ((long long)out_size - 1 - E) / (2LL * S * E);
    int CAPV = 128;
    if (c > 0 && (1 + 2LL * S * E * c + E) == (long long)out_size)
        CAPV = (int)c;
    size_t SEC = (size_t)S * E * (size_t)CAPV;

    init_kernel<<<128, 256>>>();
    fused_gemm_zero<<<NCOMPUTE + NZERO, 256>>>(in, wgt, out, (size_t)out_size);
    softmax_kernel<<<S / 256, 256>>>();
    base_kernel<<<E, 256>>>(out, SEC);
    scatter_kernel<<<S / 256, 256>>>(out, SEC, CAPV);
}